// round 1
// baseline (speedup 1.0000x reference)
#include <cuda_runtime.h>
#include <math.h>

#define T_TOK   8192
#define DM      512
#define HID     1024
#define NEXP    8

#define BM 64
#define BN 64
#define BK 16

// ---------------- scratch (static device globals; no allocation) -----------
__device__ int   g_counts[NEXP];
__device__ int   g_offsets[NEXP];
__device__ int   g_fill[NEXP];
__device__ int   g_topidx[T_TOK * 2];
__device__ float g_topw[T_TOK * 2];
__device__ int   g_slot_tok[T_TOK * 2];
__device__ float g_slot_gate[T_TOK * 2];
__device__ float g_H[(size_t)T_TOK * 2 * HID];   // 64 MB hidden activations

// ---------------- router: one warp per token -------------------------------
__global__ void router_kernel(const float* __restrict__ x,
                              const float* __restrict__ Wg,
                              const float* __restrict__ bg) {
    int gtid = blockIdx.x * blockDim.x + threadIdx.x;
    int tok  = gtid >> 5;
    int lane = threadIdx.x & 31;
    if (tok >= T_TOK) return;

    float acc[NEXP];
#pragma unroll
    for (int e = 0; e < NEXP; e++) acc[e] = 0.f;

    const float* xrow = x + (size_t)tok * DM;
    for (int k = lane; k < DM; k += 32) {
        float xv = xrow[k];
        const float* wrow = Wg + k * NEXP;
#pragma unroll
        for (int e = 0; e < NEXP; e++) acc[e] = fmaf(xv, wrow[e], acc[e]);
    }
#pragma unroll
    for (int e = 0; e < NEXP; e++) {
#pragma unroll
        for (int o = 16; o; o >>= 1)
            acc[e] += __shfl_xor_sync(0xffffffffu, acc[e], o);
    }

    if (lane == 0) {
#pragma unroll
        for (int e = 0; e < NEXP; e++) acc[e] += bg[e];
        // top-1 (lowest index wins ties, matching jax top_k)
        int e0 = 0; float v0 = acc[0];
#pragma unroll
        for (int e = 1; e < NEXP; e++) if (acc[e] > v0) { v0 = acc[e]; e0 = e; }
        // top-2
        int e1 = -1; float v1 = -3.0e38f;
#pragma unroll
        for (int e = 0; e < NEXP; e++)
            if (e != e0 && acc[e] > v1) { v1 = acc[e]; e1 = e; }

        // softmax over the two selected logits
        float p1 = 1.f / (1.f + expf(v0 - v1));
        float p0 = 1.f - p1;

        g_topidx[tok * 2 + 0] = e0;
        g_topidx[tok * 2 + 1] = e1;
        g_topw[tok * 2 + 0]   = p0;
        g_topw[tok * 2 + 1]   = p1;
        atomicAdd(&g_counts[e0], 1);
        atomicAdd(&g_counts[e1], 1);
    }
}

// ---------------- tiny init / scan / scatter -------------------------------
__global__ void init_kernel() {
    int i = threadIdx.x;
    if (i < NEXP) { g_counts[i] = 0; g_fill[i] = 0; }
}

__global__ void scan_kernel() {
    if (threadIdx.x == 0) {
        int off = 0;
        for (int e = 0; e < NEXP; e++) { g_offsets[e] = off; off += g_counts[e]; }
    }
}

__global__ void scatter_kernel() {
    int t = blockIdx.x * blockDim.x + threadIdx.x;
    if (t >= T_TOK) return;
#pragma unroll
    for (int j = 0; j < 2; j++) {
        int e = g_topidx[t * 2 + j];
        int pos = atomicAdd(&g_fill[e], 1);
        int slot = g_offsets[e] + pos;
        g_slot_tok[slot]  = t;
        g_slot_gate[slot] = g_topw[t * 2 + j];
    }
}

// ---------------- GEMM1: H = silu(x@W1) * (x@W3), gathered rows ------------
__global__ __launch_bounds__(256) void gemm1_kernel(
    const float* __restrict__ x,
    const float* __restrict__ W1,
    const float* __restrict__ W3) {
    const int e   = blockIdx.z;
    const int cnt = g_counts[e];
    const int m0  = blockIdx.y * BM;
    if (m0 >= cnt) return;
    const int base = g_offsets[e];
    const int n0   = blockIdx.x * BN;

    __shared__ float As[BK][BM + 1];
    __shared__ float B1s[BK][BN];
    __shared__ float B3s[BK][BN];

    const int tid = threadIdx.x;
    const int tx  = tid & 15;
    const int ty  = tid >> 4;

    // A loader mapping: 64 rows x 16 k, float4 along k
    const int lm = tid >> 2;
    const int lk = (tid & 3) << 2;
    int arow = m0 + lm;
    int cl   = arow < cnt ? arow : cnt - 1;
    const int tok = g_slot_tok[base + cl];
    const float* aptr = x + (size_t)tok * DM + lk;

    // B loader mapping: 16 k x 64 n, float4 along n
    const int bn = (tid & 15) << 2;
    const int bk = tid >> 4;
    const float* b1ptr = W1 + ((size_t)e * DM + bk) * HID + n0 + bn;
    const float* b3ptr = W3 + ((size_t)e * DM + bk) * HID + n0 + bn;

    float acc1[4][4] = {};
    float acc3[4][4] = {};

    for (int k0 = 0; k0 < DM; k0 += BK) {
        float4 av = *(const float4*)(aptr + k0);
        As[lk + 0][lm] = av.x;
        As[lk + 1][lm] = av.y;
        As[lk + 2][lm] = av.z;
        As[lk + 3][lm] = av.w;
        *(float4*)&B1s[bk][bn] = *(const float4*)(b1ptr + (size_t)k0 * HID);
        *(float4*)&B3s[bk][bn] = *(const float4*)(b3ptr + (size_t)k0 * HID);
        __syncthreads();
#pragma unroll
        for (int k = 0; k < BK; k++) {
            float a[4];
#pragma unroll
            for (int i = 0; i < 4; i++) a[i] = As[k][ty * 4 + i];
            float4 b1 = *(const float4*)&B1s[k][tx * 4];
            float4 b3 = *(const float4*)&B3s[k][tx * 4];
#pragma unroll
            for (int i = 0; i < 4; i++) {
                acc1[i][0] = fmaf(a[i], b1.x, acc1[i][0]);
                acc1[i][1] = fmaf(a[i], b1.y, acc1[i][1]);
                acc1[i][2] = fmaf(a[i], b1.z, acc1[i][2]);
                acc1[i][3] = fmaf(a[i], b1.w, acc1[i][3]);
                acc3[i][0] = fmaf(a[i], b3.x, acc3[i][0]);
                acc3[i][1] = fmaf(a[i], b3.y, acc3[i][1]);
                acc3[i][2] = fmaf(a[i], b3.z, acc3[i][2]);
                acc3[i][3] = fmaf(a[i], b3.w, acc3[i][3]);
            }
        }
        __syncthreads();
    }

#pragma unroll
    for (int i = 0; i < 4; i++) {
        int m = m0 + ty * 4 + i;
        if (m < cnt) {
            float* hrow = g_H + (size_t)(base + m) * HID + n0 + tx * 4;
#pragma unroll
            for (int j = 0; j < 4; j++) {
                float a = acc1[i][j];
                float h = (a / (1.f + expf(-a))) * acc3[i][j];
                hrow[j] = h;
            }
        }
    }
}

// ---------------- GEMM2: y += gate * (H @ W2), atomic scatter --------------
__global__ __launch_bounds__(256) void gemm2_kernel(
    const float* __restrict__ W2,
    float* __restrict__ y) {
    const int e   = blockIdx.z;
    const int cnt = g_counts[e];
    const int m0  = blockIdx.y * BM;
    if (m0 >= cnt) return;
    const int base = g_offsets[e];
    const int n0   = blockIdx.x * BN;

    __shared__ float As[BK][BM + 1];
    __shared__ float Bs[BK][BN];

    const int tid = threadIdx.x;
    const int tx  = tid & 15;
    const int ty  = tid >> 4;

    const int lm = tid >> 2;
    const int lk = (tid & 3) << 2;
    int arow = m0 + lm;
    int cl   = arow < cnt ? arow : cnt - 1;
    const float* aptr = g_H + (size_t)(base + cl) * HID + lk;

    const int bn = (tid & 15) << 2;
    const int bk = tid >> 4;
    const float* bptr = W2 + ((size_t)e * HID + bk) * DM + n0 + bn;

    float acc[4][4] = {};

    for (int k0 = 0; k0 < HID; k0 += BK) {
        float4 av = *(const float4*)(aptr + k0);
        As[lk + 0][lm] = av.x;
        As[lk + 1][lm] = av.y;
        As[lk + 2][lm] = av.z;
        As[lk + 3][lm] = av.w;
        *(float4*)&Bs[bk][bn] = *(const float4*)(bptr + (size_t)k0 * DM);
        __syncthreads();
#pragma unroll
        for (int k = 0; k < BK; k++) {
            float a[4];
#pragma unroll
            for (int i = 0; i < 4; i++) a[i] = As[k][ty * 4 + i];
            float4 b = *(const float4*)&Bs[k][tx * 4];
#pragma unroll
            for (int i = 0; i < 4; i++) {
                acc[i][0] = fmaf(a[i], b.x, acc[i][0]);
                acc[i][1] = fmaf(a[i], b.y, acc[i][1]);
                acc[i][2] = fmaf(a[i], b.z, acc[i][2]);
                acc[i][3] = fmaf(a[i], b.w, acc[i][3]);
            }
        }
        __syncthreads();
    }

#pragma unroll
    for (int i = 0; i < 4; i++) {
        int m = m0 + ty * 4 + i;
        if (m < cnt) {
            int   tok = g_slot_tok[base + m];
            float g   = g_slot_gate[base + m];
            float* yrow = y + (size_t)tok * DM + n0 + tx * 4;
#pragma unroll
            for (int j = 0; j < 4; j++)
                atomicAdd(&yrow[j], g * acc[i][j]);
        }
    }
}

// ---------------- launch ---------------------------------------------------
extern "C" void kernel_launch(void* const* d_in, const int* in_sizes, int n_in,
                              void* d_out, int out_size) {
    const float* x  = (const float*)d_in[0];
    const float* Wg = (const float*)d_in[1];
    const float* bg = (const float*)d_in[2];
    const float* W1 = (const float*)d_in[3];
    const float* W3 = (const float*)d_in[4];
    const float* W2 = (const float*)d_in[5];
    float* y = (float*)d_out;

    init_kernel<<<1, 32>>>();
    cudaMemsetAsync(d_out, 0, (size_t)out_size * sizeof(float));
    router_kernel<<<(T_TOK * 32) / 256, 256>>>(x, Wg, bg);
    scan_kernel<<<1, 32>>>();
    scatter_kernel<<<(T_TOK + 255) / 256, 256>>>();

    dim3 g1(HID / BN, (T_TOK + BM - 1) / BM, NEXP);
    gemm1_kernel<<<g1, 256>>>(x, W1, W3);

    dim3 g2(DM / BN, (T_TOK + BM - 1) / BM, NEXP);
    gemm2_kernel<<<g2, 256>>>(W2, y);
}